// round 1
// baseline (speedup 1.0000x reference)
#include <cuda_runtime.h>
#include <math.h>

#define H 256
#define DIN 700
#define DOUT 20
#define BATCH 128
#define TT 250

// Scratch (device globals: allocation-free rule)
__device__ float g_X1[(size_t)BATCH * TT * H];   // x@Wi1.T + bi1 + b11, [B*T, 256]
__device__ float g_W11T[H * H];
__device__ float g_W12T[H * H];
__device__ float g_W22T[H * H];

// ---------------------------------------------------------------------------
// Weight transpose: WT[j][i] = W[i][j] so a spike j reads a coalesced row.
// ---------------------------------------------------------------------------
__global__ void transpose_weights_kernel(const float* __restrict__ W11,
                                         const float* __restrict__ W12,
                                         const float* __restrict__ W22) {
    int idx = blockIdx.x * blockDim.x + threadIdx.x;   // 3*65536 threads
    int m = idx >> 16;
    int r = (idx >> 8) & 255;   // source row i
    int c = idx & 255;          // source col j
    if (m == 0)      g_W11T[c * H + r] = W11[r * H + c];
    else if (m == 1) g_W12T[c * H + r] = W12[r * H + c];
    else             g_W22T[c * H + r] = W22[r * H + c];
}

// ---------------------------------------------------------------------------
// X1 = x @ Wi1.T + (bi1 + b11).  M=32000, N=256, K=700. fp32 tiled GEMM.
// ---------------------------------------------------------------------------
#define BM 64
#define BN 64
#define BK 16

__global__ __launch_bounds__(256) void gemm_x1_kernel(
    const float* __restrict__ x, const float* __restrict__ Wi1,
    const float* __restrict__ bi1, const float* __restrict__ b11) {
    __shared__ float As[BK][BM];
    __shared__ float Bs[BK][BN];
    int tid = threadIdx.x;
    int m0 = blockIdx.y * BM;
    int n0 = blockIdx.x * BN;
    int lrow = tid >> 2;          // 0..63
    int lk = (tid & 3) * 4;       // 0,4,8,12
    int ty = tid >> 4, tx = tid & 15;

    float acc[4][4];
#pragma unroll
    for (int r = 0; r < 4; ++r)
#pragma unroll
        for (int c = 0; c < 4; ++c) acc[r][c] = 0.f;

    for (int k0 = 0; k0 < DIN; k0 += BK) {
        int k = k0 + lk;
        float4 av = make_float4(0.f, 0.f, 0.f, 0.f);
        float4 bv = make_float4(0.f, 0.f, 0.f, 0.f);
        if (k < DIN) {  // 700 % 4 == 0 -> float4 either fully valid or fully OOB
            av = *(const float4*)(x   + (size_t)(m0 + lrow) * DIN + k);
            bv = *(const float4*)(Wi1 + (size_t)(n0 + lrow) * DIN + k);
        }
        __syncthreads();
        As[lk + 0][lrow] = av.x; As[lk + 1][lrow] = av.y;
        As[lk + 2][lrow] = av.z; As[lk + 3][lrow] = av.w;
        Bs[lk + 0][lrow] = bv.x; Bs[lk + 1][lrow] = bv.y;
        Bs[lk + 2][lrow] = bv.z; Bs[lk + 3][lrow] = bv.w;
        __syncthreads();
#pragma unroll
        for (int kk = 0; kk < BK; ++kk) {
            float4 a = *(const float4*)&As[kk][ty * 4];
            float4 b = *(const float4*)&Bs[kk][tx * 4];
            float ar[4] = {a.x, a.y, a.z, a.w};
            float br[4] = {b.x, b.y, b.z, b.w};
#pragma unroll
            for (int r = 0; r < 4; ++r)
#pragma unroll
                for (int c = 0; c < 4; ++c) acc[r][c] += ar[r] * br[c];
        }
    }
#pragma unroll
    for (int r = 0; r < 4; ++r) {
        int m = m0 + ty * 4 + r;
#pragma unroll
        for (int c = 0; c < 4; ++c) {
            int n = n0 + tx * 4 + c;
            g_X1[(size_t)m * H + n] = acc[r][c] + bi1[n] + b11[n];
        }
    }
}

// ---------------------------------------------------------------------------
// Sparse spike gather: sum of W rows selected by the active list.
// 8-deep load batching for MLP against L2 latency.
// ---------------------------------------------------------------------------
__device__ __forceinline__ float gather_rows(const float* __restrict__ W,
                                             const int* lst, int cnt, int i) {
    float s0 = 0.f, s1 = 0.f, s2 = 0.f, s3 = 0.f;
    int k = 0;
    for (; k + 8 <= cnt; k += 8) {
        int j0 = lst[k + 0], j1 = lst[k + 1], j2 = lst[k + 2], j3 = lst[k + 3];
        int j4 = lst[k + 4], j5 = lst[k + 5], j6 = lst[k + 6], j7 = lst[k + 7];
        float v0 = W[j0 * H + i], v1 = W[j1 * H + i];
        float v2 = W[j2 * H + i], v3 = W[j3 * H + i];
        float v4 = W[j4 * H + i], v5 = W[j5 * H + i];
        float v6 = W[j6 * H + i], v7 = W[j7 * H + i];
        s0 += v0; s1 += v1; s2 += v2; s3 += v3;
        s0 += v4; s1 += v5; s2 += v6; s3 += v7;
    }
    for (; k < cnt; ++k) s0 += W[lst[k] * H + i];
    return (s0 + s1) + (s2 + s3);
}

// ---------------------------------------------------------------------------
// Persistent RNN: one CTA per batch sample, 256 threads (thread = neuron),
// 250 timesteps entirely inside the kernel. No inter-CTA sync.
// ---------------------------------------------------------------------------
__global__ __launch_bounds__(256) void rnn_kernel(
    const float* __restrict__ mem1_0, const float* __restrict__ mem2_0,
    const float* __restrict__ memo_0,
    const float* __restrict__ b12v, const float* __restrict__ b22v,
    const float* __restrict__ Wo, const float* __restrict__ bov,
    const float* __restrict__ tau_adp1, const float* __restrict__ tau_adp2,
    const float* __restrict__ tau_m1, const float* __restrict__ tau_m2,
    const float* __restrict__ tau_mo,
    float* __restrict__ out) {
    __shared__ int list1[2][H];
    __shared__ int list2[2][H];
    __shared__ unsigned mb1[8], mb2[8];
    __shared__ float sWo[H * DOUT];   // WoT[j][k], 20 KB

    int b = blockIdx.x;
    int i = threadIdx.x;
    int lane = i & 31, warp = i >> 5;

    // Per-neuron state in registers
    float mem1 = mem1_0[b * H + i], sp1 = 0.f, ab1 = 0.01f;
    float alpha1 = expf(-1.f / tau_m1[i]);  float oma1 = 1.f - alpha1;
    float ro1    = expf(-1.f / tau_adp1[i]); float oro1 = 1.f - ro1;
    float mem2 = mem2_0[b * H + i], sp2 = 0.f, ab2 = 0.01f;
    float alpha2 = expf(-1.f / tau_m2[i]);  float oma2 = 1.f - alpha2;
    float ro2    = expf(-1.f / tau_adp2[i]); float oro2 = 1.f - ro2;
    float hb2 = b12v[i] + b22v[i];

    float memo = 0.f, alo = 0.f, omo = 0.f, bok = 0.f, acc = 0.f;
    if (i < DOUT) {
        memo = memo_0[b * DOUT + i];
        alo = expf(-1.f / tau_mo[i]); omo = 1.f - alo;
        bok = bov[i];
    }
    // WoT into SMEM (one-time, transposed)
#pragma unroll
    for (int k = 0; k < DOUT; ++k) sWo[i * DOUT + k] = Wo[k * H + i];
    __syncthreads();

    int cnt1 = 0, cnt2 = 0;
    int p = 0;
    const float* X1base = g_X1 + (size_t)b * TT * H;

    for (int t = 0; t < TT; ++t) {
        int pn = p ^ 1;

        // ---- layer 1 ----
        float h1 = X1base[t * H + i] + gather_rows(g_W11T, list1[p], cnt1, i);
        ab1 = ro1 * ab1 + oro1 * sp1;               // uses OLD spike
        float B1 = 0.01f + 1.8f * ab1;
        mem1 = mem1 * alpha1 + oma1 * h1 - B1 * sp1;
        float sp1n = (mem1 - B1) > 0.f ? 1.f : 0.f;

        // deterministic cross-warp compaction of active indices
        unsigned bal = __ballot_sync(0xffffffffu, sp1n != 0.f);
        if (lane == 0) mb1[warp] = bal;
        __syncthreads();
        int base = 0, tot = 0;
#pragma unroll
        for (int w = 0; w < 8; ++w) {
            int c = __popc(mb1[w]);
            if (w < warp) base += c;
            tot += c;
        }
        if (sp1n != 0.f) list1[pn][base + __popc(bal & ((1u << lane) - 1u))] = i;
        int cnt1n = tot;
        __syncthreads();

        // ---- layer 2 (new sp1, old sp2) ----
        float h2 = hb2 + gather_rows(g_W12T, list1[pn], cnt1n, i)
                       + gather_rows(g_W22T, list2[p], cnt2, i);
        ab2 = ro2 * ab2 + oro2 * sp2;
        float B2 = 0.01f + 1.8f * ab2;
        mem2 = mem2 * alpha2 + oma2 * h2 - B2 * sp2;
        float sp2n = (mem2 - B2) > 0.f ? 1.f : 0.f;

        bal = __ballot_sync(0xffffffffu, sp2n != 0.f);
        if (lane == 0) mb2[warp] = bal;
        __syncthreads();
        base = 0; tot = 0;
#pragma unroll
        for (int w = 0; w < 8; ++w) {
            int c = __popc(mb2[w]);
            if (w < warp) base += c;
            tot += c;
        }
        if (sp2n != 0.f) list2[pn][base + __popc(bal & ((1u << lane) - 1u))] = i;
        int cnt2n = tot;
        __syncthreads();

        // ---- output layer + softmax accumulation (warp 0 only) ----
        if (warp == 0) {
            int k = lane < DOUT ? lane : 0;
            float o = bok;
            const int* l2 = list2[pn];
            for (int q = 0; q < cnt2n; ++q) o += sWo[l2[q] * DOUT + k];
            memo = memo * alo + omo * o;
            float mv = lane < DOUT ? memo : -INFINITY;
#pragma unroll
            for (int s = 16; s > 0; s >>= 1)
                mv = fmaxf(mv, __shfl_xor_sync(0xffffffffu, mv, s));
            float e = lane < DOUT ? expf(memo - mv) : 0.f;
            float ss = e;
#pragma unroll
            for (int s = 16; s > 0; s >>= 1)
                ss += __shfl_xor_sync(0xffffffffu, ss, s);
            if (t > 10) acc += e / ss;
        }

        sp1 = sp1n; sp2 = sp2n; cnt1 = cnt1n; cnt2 = cnt2n; p = pn;
    }

    if (i < DOUT) out[b * DOUT + i] = acc;
}

// ---------------------------------------------------------------------------
extern "C" void kernel_launch(void* const* d_in, const int* in_sizes, int n_in,
                              void* d_out, int out_size) {
    const float* x        = (const float*)d_in[0];
    const float* mem1_0   = (const float*)d_in[1];
    const float* mem2_0   = (const float*)d_in[2];
    const float* memo_0   = (const float*)d_in[3];
    const float* Wi1      = (const float*)d_in[4];
    const float* bi1      = (const float*)d_in[5];
    const float* W11      = (const float*)d_in[6];
    const float* b11      = (const float*)d_in[7];
    const float* W12      = (const float*)d_in[8];
    const float* b12      = (const float*)d_in[9];
    const float* W22      = (const float*)d_in[10];
    const float* b22      = (const float*)d_in[11];
    const float* Wo       = (const float*)d_in[12];
    const float* bo       = (const float*)d_in[13];
    const float* tau_adp1 = (const float*)d_in[14];
    const float* tau_adp2 = (const float*)d_in[15];
    const float* tau_m1   = (const float*)d_in[16];
    const float* tau_m2   = (const float*)d_in[17];
    const float* tau_mo   = (const float*)d_in[18];
    float* out = (float*)d_out;

    transpose_weights_kernel<<<(3 * H * H) / 256, 256>>>(W11, W12, W22);
    dim3 g(H / BN, (BATCH * TT) / BM);   // (4, 500)
    gemm_x1_kernel<<<g, 256>>>(x, Wi1, bi1, b11);
    rnn_kernel<<<BATCH, 256>>>(mem1_0, mem2_0, memo_0, b12, b22, Wo, bo,
                               tau_adp1, tau_adp2, tau_m1, tau_m2, tau_mo, out);
}

// round 2
// speedup vs baseline: 1.0086x; 1.0086x over previous
#include <cuda_runtime.h>
#include <math.h>

#define H 256
#define DIN 700
#define DOUT 20
#define BATCH 128
#define TT 250

// Scratch (device globals: allocation-free rule)
__device__ float g_X1[(size_t)BATCH * TT * H];   // x@Wi1.T + bi1 + b11, [B*T, 256]
__device__ float g_W11T[H * H];
__device__ float g_W12T[H * H];
__device__ float g_W22T[H * H];

// ---------------------------------------------------------------------------
// Packed fp32x2 FMA helpers (sm_103a FFMA2 — only reachable via PTX)
// ---------------------------------------------------------------------------
__device__ __forceinline__ void ffma2(unsigned long long& acc,
                                      unsigned long long a,
                                      unsigned long long b) {
    asm("fma.rn.f32x2 %0, %1, %2, %0;" : "+l"(acc) : "l"(a), "l"(b));
}
__device__ __forceinline__ unsigned long long pack2(float lo, float hi) {
    unsigned long long r;
    asm("mov.b64 %0, {%1, %2};" : "=l"(r) : "f"(lo), "f"(hi));
    return r;
}
__device__ __forceinline__ void unpack2(unsigned long long v, float& lo, float& hi) {
    asm("mov.b64 {%0, %1}, %2;" : "=f"(lo), "=f"(hi) : "l"(v));
}

// ---------------------------------------------------------------------------
// Weight transpose: WT[j][i] = W[i][j] so a spike j reads a coalesced row.
// ---------------------------------------------------------------------------
__global__ void transpose_weights_kernel(const float* __restrict__ W11,
                                         const float* __restrict__ W12,
                                         const float* __restrict__ W22) {
    int idx = blockIdx.x * blockDim.x + threadIdx.x;   // 3*65536 threads
    int m = idx >> 16;
    int r = (idx >> 8) & 255;   // source row i
    int c = idx & 255;          // source col j
    if (m == 0)      g_W11T[c * H + r] = W11[r * H + c];
    else if (m == 1) g_W12T[c * H + r] = W12[r * H + c];
    else             g_W22T[c * H + r] = W22[r * H + c];
}

// ---------------------------------------------------------------------------
// X1 = x @ Wi1.T + (bi1 + b11).  M=32000, N=256, K=700.
// 128x128 tile, BK=16, double-buffered, 8x8/thread via FFMA2.
// ---------------------------------------------------------------------------
#define GBM 128
#define GBN 128
#define GBK 16
#define GPAD 4
#define GNT ((DIN + GBK - 1) / GBK)   // 44 tiles (last partial: 12 cols)

__global__ __launch_bounds__(256) void gemm_x1_kernel(
    const float* __restrict__ x, const float* __restrict__ Wi1,
    const float* __restrict__ bi1, const float* __restrict__ b11) {
    __shared__ float As[2][GBK][GBM + GPAD];
    __shared__ float Bs[2][GBK][GBN + GPAD];

    int tid = threadIdx.x;
    int m0 = blockIdx.y * GBM;
    int n0 = blockIdx.x * GBN;
    int tx = tid & 15, ty = tid >> 4;

    // Load mapping: tile is 128 rows x 4 k-quads of float4.
    // it=0,1 : f = it*256 + tid ; row = f>>2 ; kc = f&3  (warp covers 8 rows x 4 kc)
    int row0 = tid >> 2,          kc0 = tid & 3;
    int row1 = (256 + tid) >> 2,  kc1 = tid & 3;   // (256+tid)&3 == tid&3

    // Accumulators packed along M: acc[r2][c] = (C[2r2][c], C[2r2+1][c])
    unsigned long long acc[4][8];
#pragma unroll
    for (int r = 0; r < 4; ++r)
#pragma unroll
        for (int c = 0; c < 8; ++c) acc[r][c] = 0ull;

    float4 stA0, stA1, stB0, stB1;

    // -- prologue: load tile 0 --
    {
        int kb = 0;
        int kA0 = kb + kc0 * 4, kA1 = kb + kc1 * 4;
        stA0 = (kA0 < DIN) ? *(const float4*)(x + (size_t)(m0 + row0) * DIN + kA0)
                           : make_float4(0.f, 0.f, 0.f, 0.f);
        stA1 = (kA1 < DIN) ? *(const float4*)(x + (size_t)(m0 + row1) * DIN + kA1)
                           : make_float4(0.f, 0.f, 0.f, 0.f);
        stB0 = (kA0 < DIN) ? *(const float4*)(Wi1 + (size_t)(n0 + row0) * DIN + kA0)
                           : make_float4(0.f, 0.f, 0.f, 0.f);
        stB1 = (kA1 < DIN) ? *(const float4*)(Wi1 + (size_t)(n0 + row1) * DIN + kA1)
                           : make_float4(0.f, 0.f, 0.f, 0.f);
        As[0][kc0 * 4 + 0][row0] = stA0.x; As[0][kc0 * 4 + 1][row0] = stA0.y;
        As[0][kc0 * 4 + 2][row0] = stA0.z; As[0][kc0 * 4 + 3][row0] = stA0.w;
        As[0][kc1 * 4 + 0][row1] = stA1.x; As[0][kc1 * 4 + 1][row1] = stA1.y;
        As[0][kc1 * 4 + 2][row1] = stA1.z; As[0][kc1 * 4 + 3][row1] = stA1.w;
        Bs[0][kc0 * 4 + 0][row0] = stB0.x; Bs[0][kc0 * 4 + 1][row0] = stB0.y;
        Bs[0][kc0 * 4 + 2][row0] = stB0.z; Bs[0][kc0 * 4 + 3][row0] = stB0.w;
        Bs[0][kc1 * 4 + 0][row1] = stB1.x; Bs[0][kc1 * 4 + 1][row1] = stB1.y;
        Bs[0][kc1 * 4 + 2][row1] = stB1.z; Bs[0][kc1 * 4 + 3][row1] = stB1.w;
    }
    __syncthreads();

    for (int t = 0; t < GNT; ++t) {
        int buf = t & 1;

        // prefetch tile t+1 into registers
        if (t + 1 < GNT) {
            int kb = (t + 1) * GBK;
            int kA0 = kb + kc0 * 4, kA1 = kb + kc1 * 4;
            stA0 = (kA0 < DIN) ? *(const float4*)(x + (size_t)(m0 + row0) * DIN + kA0)
                               : make_float4(0.f, 0.f, 0.f, 0.f);
            stA1 = (kA1 < DIN) ? *(const float4*)(x + (size_t)(m0 + row1) * DIN + kA1)
                               : make_float4(0.f, 0.f, 0.f, 0.f);
            stB0 = (kA0 < DIN) ? *(const float4*)(Wi1 + (size_t)(n0 + row0) * DIN + kA0)
                               : make_float4(0.f, 0.f, 0.f, 0.f);
            stB1 = (kA1 < DIN) ? *(const float4*)(Wi1 + (size_t)(n0 + row1) * DIN + kA1)
                               : make_float4(0.f, 0.f, 0.f, 0.f);
        }

        // compute on buf
#pragma unroll
        for (int kk = 0; kk < GBK; ++kk) {
            ulonglong2 aA = *(const ulonglong2*)&As[buf][kk][ty * 8];
            ulonglong2 aB = *(const ulonglong2*)&As[buf][kk][ty * 8 + 4];
            float4 b0 = *(const float4*)&Bs[buf][kk][tx * 8];
            float4 b1 = *(const float4*)&Bs[buf][kk][tx * 8 + 4];
            float barr[8] = {b0.x, b0.y, b0.z, b0.w, b1.x, b1.y, b1.z, b1.w};
#pragma unroll
            for (int c = 0; c < 8; ++c) {
                unsigned long long bb = pack2(barr[c], barr[c]);
                ffma2(acc[0][c], aA.x, bb);
                ffma2(acc[1][c], aA.y, bb);
                ffma2(acc[2][c], aB.x, bb);
                ffma2(acc[3][c], aB.y, bb);
            }
        }

        // store prefetched tile into the other buffer
        if (t + 1 < GNT) {
            int nb = buf ^ 1;
            As[nb][kc0 * 4 + 0][row0] = stA0.x; As[nb][kc0 * 4 + 1][row0] = stA0.y;
            As[nb][kc0 * 4 + 2][row0] = stA0.z; As[nb][kc0 * 4 + 3][row0] = stA0.w;
            As[nb][kc1 * 4 + 0][row1] = stA1.x; As[nb][kc1 * 4 + 1][row1] = stA1.y;
            As[nb][kc1 * 4 + 2][row1] = stA1.z; As[nb][kc1 * 4 + 3][row1] = stA1.w;
            Bs[nb][kc0 * 4 + 0][row0] = stB0.x; Bs[nb][kc0 * 4 + 1][row0] = stB0.y;
            Bs[nb][kc0 * 4 + 2][row0] = stB0.z; Bs[nb][kc0 * 4 + 3][row0] = stB0.w;
            Bs[nb][kc1 * 4 + 0][row1] = stB1.x; Bs[nb][kc1 * 4 + 1][row1] = stB1.y;
            Bs[nb][kc1 * 4 + 2][row1] = stB1.z; Bs[nb][kc1 * 4 + 3][row1] = stB1.w;
        }
        __syncthreads();
    }

    // epilogue: unpack, add bias, store
    float bias[8];
#pragma unroll
    for (int c = 0; c < 8; ++c) {
        int n = n0 + tx * 8 + c;
        bias[c] = bi1[n] + b11[n];
    }
#pragma unroll
    for (int r2 = 0; r2 < 4; ++r2) {
        float lo[8], hi[8];
#pragma unroll
        for (int c = 0; c < 8; ++c) unpack2(acc[r2][c], lo[c], hi[c]);
        int mA = m0 + ty * 8 + 2 * r2;
        int mB = mA + 1;
        int n = n0 + tx * 8;
        float4* pA = (float4*)(g_X1 + (size_t)mA * H + n);
        float4* pB = (float4*)(g_X1 + (size_t)mB * H + n);
        pA[0] = make_float4(lo[0] + bias[0], lo[1] + bias[1], lo[2] + bias[2], lo[3] + bias[3]);
        pA[1] = make_float4(lo[4] + bias[4], lo[5] + bias[5], lo[6] + bias[6], lo[7] + bias[7]);
        pB[0] = make_float4(hi[0] + bias[0], hi[1] + bias[1], hi[2] + bias[2], hi[3] + bias[3]);
        pB[1] = make_float4(hi[4] + bias[4], hi[5] + bias[5], hi[6] + bias[6], hi[7] + bias[7]);
    }
}

// ---------------------------------------------------------------------------
// Sparse spike gather: sum of W rows selected by the active list.
// 8-deep load batching for MLP against L2 latency.
// ---------------------------------------------------------------------------
__device__ __forceinline__ float gather_rows(const float* __restrict__ W,
                                             const int* lst, int cnt, int i) {
    float s0 = 0.f, s1 = 0.f, s2 = 0.f, s3 = 0.f;
    int k = 0;
    for (; k + 8 <= cnt; k += 8) {
        int j0 = lst[k + 0], j1 = lst[k + 1], j2 = lst[k + 2], j3 = lst[k + 3];
        int j4 = lst[k + 4], j5 = lst[k + 5], j6 = lst[k + 6], j7 = lst[k + 7];
        float v0 = W[j0 * H + i], v1 = W[j1 * H + i];
        float v2 = W[j2 * H + i], v3 = W[j3 * H + i];
        float v4 = W[j4 * H + i], v5 = W[j5 * H + i];
        float v6 = W[j6 * H + i], v7 = W[j7 * H + i];
        s0 += v0; s1 += v1; s2 += v2; s3 += v3;
        s0 += v4; s1 += v5; s2 += v6; s3 += v7;
    }
    for (; k < cnt; ++k) s0 += W[lst[k] * H + i];
    return (s0 + s1) + (s2 + s3);
}

// ---------------------------------------------------------------------------
// Persistent RNN: one CTA per batch sample, 256 threads (thread = neuron),
// 250 timesteps entirely inside the kernel. No inter-CTA sync.
// ---------------------------------------------------------------------------
__global__ __launch_bounds__(256) void rnn_kernel(
    const float* __restrict__ mem1_0, const float* __restrict__ mem2_0,
    const float* __restrict__ memo_0,
    const float* __restrict__ b12v, const float* __restrict__ b22v,
    const float* __restrict__ Wo, const float* __restrict__ bov,
    const float* __restrict__ tau_adp1, const float* __restrict__ tau_adp2,
    const float* __restrict__ tau_m1, const float* __restrict__ tau_m2,
    const float* __restrict__ tau_mo,
    float* __restrict__ out) {
    __shared__ int list1[2][H];
    __shared__ int list2[2][H];
    __shared__ unsigned mb1[8], mb2[8];
    __shared__ float sWo[H * DOUT];   // WoT[j][k], 20 KB

    int b = blockIdx.x;
    int i = threadIdx.x;
    int lane = i & 31, warp = i >> 5;

    // Per-neuron state in registers
    float mem1 = mem1_0[b * H + i], sp1 = 0.f, ab1 = 0.01f;
    float alpha1 = expf(-1.f / tau_m1[i]);  float oma1 = 1.f - alpha1;
    float ro1    = expf(-1.f / tau_adp1[i]); float oro1 = 1.f - ro1;
    float mem2 = mem2_0[b * H + i], sp2 = 0.f, ab2 = 0.01f;
    float alpha2 = expf(-1.f / tau_m2[i]);  float oma2 = 1.f - alpha2;
    float ro2    = expf(-1.f / tau_adp2[i]); float oro2 = 1.f - ro2;
    float hb2 = b12v[i] + b22v[i];

    float memo = 0.f, alo = 0.f, omo = 0.f, bok = 0.f, acc = 0.f;
    if (i < DOUT) {
        memo = memo_0[b * DOUT + i];
        alo = expf(-1.f / tau_mo[i]); omo = 1.f - alo;
        bok = bov[i];
    }
    // WoT into SMEM (one-time, transposed)
#pragma unroll
    for (int k = 0; k < DOUT; ++k) sWo[i * DOUT + k] = Wo[k * H + i];
    __syncthreads();

    int cnt1 = 0, cnt2 = 0;
    int p = 0;
    const float* X1base = g_X1 + (size_t)b * TT * H;

    for (int t = 0; t < TT; ++t) {
        int pn = p ^ 1;

        // ---- layer 1 ----
        float h1 = X1base[t * H + i] + gather_rows(g_W11T, list1[p], cnt1, i);
        ab1 = ro1 * ab1 + oro1 * sp1;               // uses OLD spike
        float B1 = 0.01f + 1.8f * ab1;
        mem1 = mem1 * alpha1 + oma1 * h1 - B1 * sp1;
        float sp1n = (mem1 - B1) > 0.f ? 1.f : 0.f;

        // deterministic cross-warp compaction of active indices
        unsigned bal = __ballot_sync(0xffffffffu, sp1n != 0.f);
        if (lane == 0) mb1[warp] = bal;
        __syncthreads();
        int base = 0, tot = 0;
#pragma unroll
        for (int w = 0; w < 8; ++w) {
            int c = __popc(mb1[w]);
            if (w < warp) base += c;
            tot += c;
        }
        if (sp1n != 0.f) list1[pn][base + __popc(bal & ((1u << lane) - 1u))] = i;
        int cnt1n = tot;
        __syncthreads();

        // ---- layer 2 (new sp1, old sp2) ----
        float h2 = hb2 + gather_rows(g_W12T, list1[pn], cnt1n, i)
                       + gather_rows(g_W22T, list2[p], cnt2, i);
        ab2 = ro2 * ab2 + oro2 * sp2;
        float B2 = 0.01f + 1.8f * ab2;
        mem2 = mem2 * alpha2 + oma2 * h2 - B2 * sp2;
        float sp2n = (mem2 - B2) > 0.f ? 1.f : 0.f;

        bal = __ballot_sync(0xffffffffu, sp2n != 0.f);
        if (lane == 0) mb2[warp] = bal;
        __syncthreads();
        base = 0; tot = 0;
#pragma unroll
        for (int w = 0; w < 8; ++w) {
            int c = __popc(mb2[w]);
            if (w < warp) base += c;
            tot += c;
        }
        if (sp2n != 0.f) list2[pn][base + __popc(bal & ((1u << lane) - 1u))] = i;
        int cnt2n = tot;
        __syncthreads();

        // ---- output layer + softmax accumulation (warp 0 only) ----
        if (warp == 0) {
            int k = lane < DOUT ? lane : 0;
            float o = bok;
            const int* l2 = list2[pn];
            for (int q = 0; q < cnt2n; ++q) o += sWo[l2[q] * DOUT + k];
            memo = memo * alo + omo * o;
            float mv = lane < DOUT ? memo : -INFINITY;
#pragma unroll
            for (int s = 16; s > 0; s >>= 1)
                mv = fmaxf(mv, __shfl_xor_sync(0xffffffffu, mv, s));
            float e = lane < DOUT ? expf(memo - mv) : 0.f;
            float ss = e;
#pragma unroll
            for (int s = 16; s > 0; s >>= 1)
                ss += __shfl_xor_sync(0xffffffffu, ss, s);
            if (t > 10) acc += e / ss;
        }

        sp1 = sp1n; sp2 = sp2n; cnt1 = cnt1n; cnt2 = cnt2n; p = pn;
    }

    if (i < DOUT) out[b * DOUT + i] = acc;
}

// ---------------------------------------------------------------------------
extern "C" void kernel_launch(void* const* d_in, const int* in_sizes, int n_in,
                              void* d_out, int out_size) {
    const float* x        = (const float*)d_in[0];
    const float* mem1_0   = (const float*)d_in[1];
    const float* mem2_0   = (const float*)d_in[2];
    const float* memo_0   = (const float*)d_in[3];
    const float* Wi1      = (const float*)d_in[4];
    const float* bi1      = (const float*)d_in[5];
    const float* W11      = (const float*)d_in[6];
    const float* b11      = (const float*)d_in[7];
    const float* W12      = (const float*)d_in[8];
    const float* b12      = (const float*)d_in[9];
    const float* W22      = (const float*)d_in[10];
    const float* b22      = (const float*)d_in[11];
    const float* Wo       = (const float*)d_in[12];
    const float* bo       = (const float*)d_in[13];
    const float* tau_adp1 = (const float*)d_in[14];
    const float* tau_adp2 = (const float*)d_in[15];
    const float* tau_m1   = (const float*)d_in[16];
    const float* tau_m2   = (const float*)d_in[17];
    const float* tau_mo   = (const float*)d_in[18];
    float* out = (float*)d_out;

    transpose_weights_kernel<<<(3 * H * H) / 256, 256>>>(W11, W12, W22);
    dim3 g(H / GBN, (BATCH * TT) / GBM);   // (2, 250)
    gemm_x1_kernel<<<g, 256>>>(x, Wi1, bi1, b11);
    rnn_kernel<<<BATCH, 256>>>(mem1_0, mem2_0, memo_0, b12, b22, Wo, bo,
                               tau_adp1, tau_adp2, tau_m1, tau_m2, tau_mo, out);
}

// round 3
// speedup vs baseline: 1.0738x; 1.0647x over previous
#include <cuda_runtime.h>
#include <math.h>

#define H 256
#define DIN 700
#define DOUT 20
#define BATCH 128
#define TT 250

// Scratch (device globals: allocation-free rule)
__device__ float g_X1[(size_t)BATCH * TT * H];   // x@Wi1.T + bi1 + b11, [B*T, 256]
__device__ float g_W11T[H * H];
__device__ float g_W12T[H * H];
__device__ float g_W22T[H * H];

// ---------------------------------------------------------------------------
// Packed fp32x2 FMA helpers (sm_103a FFMA2 — only reachable via PTX)
// ---------------------------------------------------------------------------
__device__ __forceinline__ void ffma2(unsigned long long& acc,
                                      unsigned long long a,
                                      unsigned long long b) {
    asm("fma.rn.f32x2 %0, %1, %2, %0;" : "+l"(acc) : "l"(a), "l"(b));
}
__device__ __forceinline__ unsigned long long pack2(float lo, float hi) {
    unsigned long long r;
    asm("mov.b64 %0, {%1, %2};" : "=l"(r) : "f"(lo), "f"(hi));
    return r;
}
__device__ __forceinline__ void unpack2(unsigned long long v, float& lo, float& hi) {
    asm("mov.b64 {%0, %1}, %2;" : "=f"(lo), "=f"(hi) : "l"(v));
}

// ---------------------------------------------------------------------------
// Weight transpose: WT[j][i] = W[i][j] so a spike j reads a coalesced row.
// ---------------------------------------------------------------------------
__global__ void transpose_weights_kernel(const float* __restrict__ W11,
                                         const float* __restrict__ W12,
                                         const float* __restrict__ W22) {
    int idx = blockIdx.x * blockDim.x + threadIdx.x;   // 3*65536 threads
    int m = idx >> 16;
    int r = (idx >> 8) & 255;   // source row i
    int c = idx & 255;          // source col j
    if (m == 0)      g_W11T[c * H + r] = W11[r * H + c];
    else if (m == 1) g_W12T[c * H + r] = W12[r * H + c];
    else             g_W22T[c * H + r] = W22[r * H + c];
}

// ---------------------------------------------------------------------------
// X1 = x @ Wi1.T + (bi1 + b11).  M=32000, N=256, K=700.
// 128x128 tile, BK=16, double-buffered, 8x8/thread via FFMA2.
// ---------------------------------------------------------------------------
#define GBM 128
#define GBN 128
#define GBK 16
#define GPAD 4
#define GNT ((DIN + GBK - 1) / GBK)   // 44 tiles (last partial: 12 cols)

__global__ __launch_bounds__(256) void gemm_x1_kernel(
    const float* __restrict__ x, const float* __restrict__ Wi1,
    const float* __restrict__ bi1, const float* __restrict__ b11) {
    __shared__ float As[2][GBK][GBM + GPAD];
    __shared__ float Bs[2][GBK][GBN + GPAD];

    int tid = threadIdx.x;
    int m0 = blockIdx.y * GBM;
    int n0 = blockIdx.x * GBN;
    int tx = tid & 15, ty = tid >> 4;

    int row0 = tid >> 2,          kc0 = tid & 3;
    int row1 = (256 + tid) >> 2,  kc1 = tid & 3;

    unsigned long long acc[4][8];
#pragma unroll
    for (int r = 0; r < 4; ++r)
#pragma unroll
        for (int c = 0; c < 8; ++c) acc[r][c] = 0ull;

    float4 stA0, stA1, stB0, stB1;

    {
        int kA0 = kc0 * 4, kA1 = kc1 * 4;
        stA0 = *(const float4*)(x   + (size_t)(m0 + row0) * DIN + kA0);
        stA1 = *(const float4*)(x   + (size_t)(m0 + row1) * DIN + kA1);
        stB0 = *(const float4*)(Wi1 + (size_t)(n0 + row0) * DIN + kA0);
        stB1 = *(const float4*)(Wi1 + (size_t)(n0 + row1) * DIN + kA1);
        As[0][kc0 * 4 + 0][row0] = stA0.x; As[0][kc0 * 4 + 1][row0] = stA0.y;
        As[0][kc0 * 4 + 2][row0] = stA0.z; As[0][kc0 * 4 + 3][row0] = stA0.w;
        As[0][kc1 * 4 + 0][row1] = stA1.x; As[0][kc1 * 4 + 1][row1] = stA1.y;
        As[0][kc1 * 4 + 2][row1] = stA1.z; As[0][kc1 * 4 + 3][row1] = stA1.w;
        Bs[0][kc0 * 4 + 0][row0] = stB0.x; Bs[0][kc0 * 4 + 1][row0] = stB0.y;
        Bs[0][kc0 * 4 + 2][row0] = stB0.z; Bs[0][kc0 * 4 + 3][row0] = stB0.w;
        Bs[0][kc1 * 4 + 0][row1] = stB1.x; Bs[0][kc1 * 4 + 1][row1] = stB1.y;
        Bs[0][kc1 * 4 + 2][row1] = stB1.z; Bs[0][kc1 * 4 + 3][row1] = stB1.w;
    }
    __syncthreads();

    for (int t = 0; t < GNT; ++t) {
        int buf = t & 1;

        if (t + 1 < GNT) {
            int kb = (t + 1) * GBK;
            int kA0 = kb + kc0 * 4, kA1 = kb + kc1 * 4;
            stA0 = (kA0 < DIN) ? *(const float4*)(x + (size_t)(m0 + row0) * DIN + kA0)
                               : make_float4(0.f, 0.f, 0.f, 0.f);
            stA1 = (kA1 < DIN) ? *(const float4*)(x + (size_t)(m0 + row1) * DIN + kA1)
                               : make_float4(0.f, 0.f, 0.f, 0.f);
            stB0 = (kA0 < DIN) ? *(const float4*)(Wi1 + (size_t)(n0 + row0) * DIN + kA0)
                               : make_float4(0.f, 0.f, 0.f, 0.f);
            stB1 = (kA1 < DIN) ? *(const float4*)(Wi1 + (size_t)(n0 + row1) * DIN + kA1)
                               : make_float4(0.f, 0.f, 0.f, 0.f);
        }

#pragma unroll
        for (int kk = 0; kk < GBK; ++kk) {
            ulonglong2 aA = *(const ulonglong2*)&As[buf][kk][ty * 8];
            ulonglong2 aB = *(const ulonglong2*)&As[buf][kk][ty * 8 + 4];
            float4 b0 = *(const float4*)&Bs[buf][kk][tx * 8];
            float4 b1 = *(const float4*)&Bs[buf][kk][tx * 8 + 4];
            float barr[8] = {b0.x, b0.y, b0.z, b0.w, b1.x, b1.y, b1.z, b1.w};
#pragma unroll
            for (int c = 0; c < 8; ++c) {
                unsigned long long bb = pack2(barr[c], barr[c]);
                ffma2(acc[0][c], aA.x, bb);
                ffma2(acc[1][c], aA.y, bb);
                ffma2(acc[2][c], aB.x, bb);
                ffma2(acc[3][c], aB.y, bb);
            }
        }

        if (t + 1 < GNT) {
            int nb = buf ^ 1;
            As[nb][kc0 * 4 + 0][row0] = stA0.x; As[nb][kc0 * 4 + 1][row0] = stA0.y;
            As[nb][kc0 * 4 + 2][row0] = stA0.z; As[nb][kc0 * 4 + 3][row0] = stA0.w;
            As[nb][kc1 * 4 + 0][row1] = stA1.x; As[nb][kc1 * 4 + 1][row1] = stA1.y;
            As[nb][kc1 * 4 + 2][row1] = stA1.z; As[nb][kc1 * 4 + 3][row1] = stA1.w;
            Bs[nb][kc0 * 4 + 0][row0] = stB0.x; Bs[nb][kc0 * 4 + 1][row0] = stB0.y;
            Bs[nb][kc0 * 4 + 2][row0] = stB0.z; Bs[nb][kc0 * 4 + 3][row0] = stB0.w;
            Bs[nb][kc1 * 4 + 0][row1] = stB1.x; Bs[nb][kc1 * 4 + 1][row1] = stB1.y;
            Bs[nb][kc1 * 4 + 2][row1] = stB1.z; Bs[nb][kc1 * 4 + 3][row1] = stB1.w;
        }
        __syncthreads();
    }

    float bias[8];
#pragma unroll
    for (int c = 0; c < 8; ++c) {
        int n = n0 + tx * 8 + c;
        bias[c] = bi1[n] + b11[n];
    }
#pragma unroll
    for (int r2 = 0; r2 < 4; ++r2) {
        float lo[8], hi[8];
#pragma unroll
        for (int c = 0; c < 8; ++c) unpack2(acc[r2][c], lo[c], hi[c]);
        int mA = m0 + ty * 8 + 2 * r2;
        int mB = mA + 1;
        int n = n0 + tx * 8;
        float4* pA = (float4*)(g_X1 + (size_t)mA * H + n);
        float4* pB = (float4*)(g_X1 + (size_t)mB * H + n);
        pA[0] = make_float4(lo[0] + bias[0], lo[1] + bias[1], lo[2] + bias[2], lo[3] + bias[3]);
        pA[1] = make_float4(lo[4] + bias[4], lo[5] + bias[5], lo[6] + bias[6], lo[7] + bias[7]);
        pB[0] = make_float4(hi[0] + bias[0], hi[1] + bias[1], hi[2] + bias[2], hi[3] + bias[3]);
        pB[1] = make_float4(hi[4] + bias[4], hi[5] + bias[5], hi[6] + bias[6], hi[7] + bias[7]);
    }
}

// ---------------------------------------------------------------------------
// Strided sparse gather: thread handles list items rep, rep+4, rep+8, ...
// 8-deep load batching for MLP against L2 latency.
// ---------------------------------------------------------------------------
__device__ __forceinline__ float gather4(const float* __restrict__ W,
                                         const int* lst, int cnt, int i, int rep) {
    float s0 = 0.f, s1 = 0.f, s2 = 0.f, s3 = 0.f;
    int k = rep;
    for (; k + 28 < cnt; k += 32) {
        int j0 = lst[k + 0],  j1 = lst[k + 4],  j2 = lst[k + 8],  j3 = lst[k + 12];
        int j4 = lst[k + 16], j5 = lst[k + 20], j6 = lst[k + 24], j7 = lst[k + 28];
        float v0 = W[j0 * H + i], v1 = W[j1 * H + i];
        float v2 = W[j2 * H + i], v3 = W[j3 * H + i];
        float v4 = W[j4 * H + i], v5 = W[j5 * H + i];
        float v6 = W[j6 * H + i], v7 = W[j7 * H + i];
        s0 += v0; s1 += v1; s2 += v2; s3 += v3;
        s0 += v4; s1 += v5; s2 += v6; s3 += v7;
    }
    for (; k < cnt; k += 4) s0 += W[lst[k] * H + i];
    return (s0 + s1) + (s2 + s3);
}

// ---------------------------------------------------------------------------
// Persistent RNN: one CTA per batch sample, 1024 threads.
// rep = tid>>8 (0..3): 4 threads cooperate per neuron i = tid&255.
// Neuron state lives in rep==0 threads; reps 1-3 are gather helpers.
// W22 gather (old sp2) fused with W11 gather -> 2 dependent gather phases.
// ---------------------------------------------------------------------------
__global__ __launch_bounds__(1024) void rnn_kernel(
    const float* __restrict__ mem1_0, const float* __restrict__ mem2_0,
    const float* __restrict__ memo_0,
    const float* __restrict__ b12v, const float* __restrict__ b22v,
    const float* __restrict__ Wo, const float* __restrict__ bov,
    const float* __restrict__ tau_adp1, const float* __restrict__ tau_adp2,
    const float* __restrict__ tau_m1, const float* __restrict__ tau_m2,
    const float* __restrict__ tau_mo,
    float* __restrict__ out) {
    __shared__ int list1[2][H];
    __shared__ int list2[2][H];
    __shared__ unsigned mb1[8], mb2[8];
    __shared__ float part11[3][H];
    __shared__ float part22[3][H];
    __shared__ float part12[3][H];
    __shared__ float sWo[H * DOUT];   // WoT[j][k], 20 KB

    int b = blockIdx.x;
    int tid = threadIdx.x;
    int i = tid & 255;
    int rep = tid >> 8;          // 0..3
    int lane = tid & 31, warp = tid >> 5;   // warps 0..7 are rep 0

    // Per-neuron state (rep 0 only)
    float mem1 = 0.f, sp1 = 0.f, ab1 = 0.01f, alpha1 = 0.f, oma1 = 0.f, ro1 = 0.f, oro1 = 0.f;
    float mem2 = 0.f, sp2 = 0.f, ab2 = 0.01f, alpha2 = 0.f, oma2 = 0.f, ro2 = 0.f, oro2 = 0.f;
    float hb2 = 0.f;
    float memo = 0.f, alo = 0.f, omo = 0.f, bok = 0.f, acc = 0.f;

    if (rep == 0) {
        mem1 = mem1_0[b * H + i];
        alpha1 = expf(-1.f / tau_m1[i]);  oma1 = 1.f - alpha1;
        ro1    = expf(-1.f / tau_adp1[i]); oro1 = 1.f - ro1;
        mem2 = mem2_0[b * H + i];
        alpha2 = expf(-1.f / tau_m2[i]);  oma2 = 1.f - alpha2;
        ro2    = expf(-1.f / tau_adp2[i]); oro2 = 1.f - ro2;
        hb2 = b12v[i] + b22v[i];
        if (i < DOUT) {
            memo = memo_0[b * DOUT + i];
            alo = expf(-1.f / tau_mo[i]); omo = 1.f - alo;
            bok = bov[i];
        }
        // WoT into SMEM (one-time, transposed)
#pragma unroll
        for (int k = 0; k < DOUT; ++k) sWo[i * DOUT + k] = Wo[k * H + i];
    }
    __syncthreads();

    int cnt1 = 0, cnt2 = 0;
    int p = 0;
    const float* X1base = g_X1 + (size_t)b * TT * H;

    // X1 prefetch (rep 0): keep the streaming DRAM load off the critical path
    float x1cur = (rep == 0) ? X1base[i] : 0.f;

    for (int t = 0; t < TT; ++t) {
        int pn = p ^ 1;

        // prefetch next step's X1 early
        float x1nxt = 0.f;
        if (rep == 0 && t + 1 < TT) x1nxt = X1base[(t + 1) * H + i];

        // ---- phase A: W11 gather (old sp1) + W22 gather (old sp2), all reps ----
        float p11 = gather4(g_W11T, list1[p], cnt1, i, rep);
        float p22 = gather4(g_W22T, list2[p], cnt2, i, rep);
        if (rep) { part11[rep - 1][i] = p11; part22[rep - 1][i] = p22; }
        __syncthreads();

        // ---- layer 1 threshold (rep 0) ----
        float sp1n = 0.f;
        if (rep == 0) {
            float h1 = x1cur + p11 + part11[0][i] + part11[1][i] + part11[2][i];
            ab1 = ro1 * ab1 + oro1 * sp1;
            float B1 = 0.01f + 1.8f * ab1;
            mem1 = mem1 * alpha1 + oma1 * h1 - B1 * sp1;
            sp1n = (mem1 - B1) > 0.f ? 1.f : 0.f;
            unsigned bal = __ballot_sync(0xffffffffu, sp1n != 0.f);
            if (lane == 0) mb1[warp] = bal;
        }
        __syncthreads();
        // compaction (all threads compute count; rep0 writes entries)
        int cnt1n;
        {
            int base = 0, tot = 0;
#pragma unroll
            for (int w = 0; w < 8; ++w) {
                int c = __popc(mb1[w]);
                if (w < warp) base += c;
                tot += c;
            }
            if (rep == 0 && sp1n != 0.f) {
                unsigned bal = mb1[warp];
                list1[pn][base + __popc(bal & ((1u << lane) - 1u))] = i;
            }
            cnt1n = tot;
        }
        __syncthreads();

        // ---- phase B: W12 gather (new sp1), all reps ----
        float p12 = gather4(g_W12T, list1[pn], cnt1n, i, rep);
        if (rep) part12[rep - 1][i] = p12;
        __syncthreads();

        // ---- layer 2 threshold (rep 0) ----
        float sp2n = 0.f;
        if (rep == 0) {
            float h2 = hb2 + p12 + part12[0][i] + part12[1][i] + part12[2][i]
                     + p22 + part22[0][i] + part22[1][i] + part22[2][i];
            ab2 = ro2 * ab2 + oro2 * sp2;
            float B2 = 0.01f + 1.8f * ab2;
            mem2 = mem2 * alpha2 + oma2 * h2 - B2 * sp2;
            sp2n = (mem2 - B2) > 0.f ? 1.f : 0.f;
            unsigned bal = __ballot_sync(0xffffffffu, sp2n != 0.f);
            if (lane == 0) mb2[warp] = bal;
        }
        __syncthreads();
        int cnt2n;
        {
            int base = 0, tot = 0;
#pragma unroll
            for (int w = 0; w < 8; ++w) {
                int c = __popc(mb2[w]);
                if (w < warp) base += c;
                tot += c;
            }
            if (rep == 0 && sp2n != 0.f) {
                unsigned bal = mb2[warp];
                list2[pn][base + __popc(bal & ((1u << lane) - 1u))] = i;
            }
            cnt2n = tot;
        }
        __syncthreads();

        // ---- output layer + softmax accumulation (warp 0 only); other warps
        //      run ahead into next step's phase A gathers ----
        if (warp == 0) {
            int k = lane < DOUT ? lane : 0;
            float o = bok;
            const int* l2 = list2[pn];
            for (int q = 0; q < cnt2n; ++q) o += sWo[l2[q] * DOUT + k];
            memo = memo * alo + omo * o;
            float mv = lane < DOUT ? memo : -INFINITY;
#pragma unroll
            for (int s = 16; s > 0; s >>= 1)
                mv = fmaxf(mv, __shfl_xor_sync(0xffffffffu, mv, s));
            float e = lane < DOUT ? expf(memo - mv) : 0.f;
            float ss = e;
#pragma unroll
            for (int s = 16; s > 0; s >>= 1)
                ss += __shfl_xor_sync(0xffffffffu, ss, s);
            if (t > 10) acc += e / ss;
        }

        sp1 = sp1n; sp2 = sp2n; cnt1 = cnt1n; cnt2 = cnt2n; p = pn;
        x1cur = x1nxt;
    }

    if (rep == 0 && i < DOUT) out[b * DOUT + i] = acc;
}

// ---------------------------------------------------------------------------
extern "C" void kernel_launch(void* const* d_in, const int* in_sizes, int n_in,
                              void* d_out, int out_size) {
    const float* x        = (const float*)d_in[0];
    const float* mem1_0   = (const float*)d_in[1];
    const float* mem2_0   = (const float*)d_in[2];
    const float* memo_0   = (const float*)d_in[3];
    const float* Wi1      = (const float*)d_in[4];
    const float* bi1      = (const float*)d_in[5];
    const float* W11      = (const float*)d_in[6];
    const float* b11      = (const float*)d_in[7];
    const float* W12      = (const float*)d_in[8];
    const float* b12      = (const float*)d_in[9];
    const float* W22      = (const float*)d_in[10];
    const float* b22      = (const float*)d_in[11];
    const float* Wo       = (const float*)d_in[12];
    const float* bo       = (const float*)d_in[13];
    const float* tau_adp1 = (const float*)d_in[14];
    const float* tau_adp2 = (const float*)d_in[15];
    const float* tau_m1   = (const float*)d_in[16];
    const float* tau_m2   = (const float*)d_in[17];
    const float* tau_mo   = (const float*)d_in[18];
    float* out = (float*)d_out;

    transpose_weights_kernel<<<(3 * H * H) / 256, 256>>>(W11, W12, W22);
    dim3 g(H / GBN, (BATCH * TT) / GBM);   // (2, 250)
    gemm_x1_kernel<<<g, 256>>>(x, Wi1, bi1, b11);
    rnn_kernel<<<BATCH, 1024>>>(mem1_0, mem2_0, memo_0, b12, b22, Wo, bo,
                                tau_adp1, tau_adp2, tau_m1, tau_m2, tau_mo, out);
}